// round 15
// baseline (speedup 1.0000x reference)
#include <cuda_runtime.h>
#include <cuda_fp16.h>
#include <math.h>

#define BS 32
#define NSAMP 64000
#define NTOT (BS*NSAMP)
#define TPB 128
#define TILE 256               // samples per CTA (2 per thread)
#define BLK 16                 // XLA ReduceWindowRewriter base_length
#define NB1 (NSAMP/BLK)        // 4000 level-1 blocks per row
#define NB2 (NB1/BLK)          // 250 level-2 blocks
#define NB2P 256               // padded to multiple of 16
#define NB3 (NB2P/BLK)         // 16

__device__ float g_S1[BS*NB1];   // level-1 block sums
__device__ float g_off1[BS*NB1]; // exclusive offset for each level-1 block

typedef unsigned long long u64;

__device__ __forceinline__ float ex2f(float x){ float r; asm("ex2.approx.f32 %0, %1;":"=f"(r):"f"(x)); return r; }
__device__ __forceinline__ float lg2f(float x){ float r; asm("lg2.approx.f32 %0, %1;":"=f"(r):"f"(x)); return r; }

// ---- packed f32x2 helpers ----
__device__ __forceinline__ u64 pack2(float lo, float hi){ u64 r; asm("mov.b64 %0, {%1,%2};":"=l"(r):"f"(lo),"f"(hi)); return r; }
__device__ __forceinline__ void unpack2(u64 v, float& lo, float& hi){ asm("mov.b64 {%0,%1}, %2;":"=f"(lo),"=f"(hi):"l"(v)); }
__device__ __forceinline__ u64 fma2(u64 a,u64 b,u64 c){ u64 r; asm("fma.rn.f32x2 %0,%1,%2,%3;":"=l"(r):"l"(a),"l"(b),"l"(c)); return r; }
__device__ __forceinline__ u64 mul2(u64 a,u64 b){ u64 r; asm("mul.rn.f32x2 %0,%1,%2;":"=l"(r):"l"(a),"l"(b)); return r; }
__device__ __forceinline__ u64 add2(u64 a,u64 b){ u64 r; asm("add.rn.f32x2 %0,%1,%2;":"=l"(r):"l"(a),"l"(b)); return r; }

// pack two f32 into a half2 register in one cvt
__device__ __forceinline__ unsigned int f2h2(float a, float b){
    unsigned int r; asm("cvt.rn.f16x2.f32 %0, %2, %1;":"=r"(r):"f"(a),"f"(b)); return r;
}

// 2*sigmoid(x)^ln10 (merged tail; +1e-7 dropped: <=1e-7 abs error).
// NOTE: hfast(-100) -> ex2(+144)=inf -> lg2(inf)=inf -> ex2(-inf)=0 exactly,
// which is what the tail-masking below relies on.
__device__ __forceinline__ float hfast(float x){
    float e = ex2f(-1.4426950408889634f * x);
    float u = lg2f(1.0f + e);
    return ex2f(fmaf(u, -2.3025850929940457f, 1.0f));
}
// full variant for total_amplitude
__device__ __forceinline__ float hfull(float x){
    float e = ex2f(-1.4426950408889634f * x);
    float u = lg2f(1.0f + e);
    return fmaf(2.0f, ex2f(-2.3025850929940457f * u), 1e-7f);
}

// increment: fast-math (arcp) form
__device__ __forceinline__ float incr(float f){
    const float RINV = 1.0f / 44100.0f;
    return __fmul_rn(__fmul_rn(6.283185307179586f, f), RINV);
}

// ---------------------------------------------------------------------------
// Kernel A: level-1 block sums S1
// ---------------------------------------------------------------------------
__global__ void __launch_bounds__(TPB) prep_kernel(const float* __restrict__ f0){
    int j = blockIdx.x * blockDim.x + threadIdx.x;
    if (j >= BS * NB1) return;
    const float4* fp = (const float4*)(f0 + (size_t)j * BLK);
    float acc = 0.0f;
    #pragma unroll
    for (int i = 0; i < BLK/4; i++){
        float4 v = fp[i];
        float d0 = incr(v.x), d1 = incr(v.y), d2 = incr(v.z), d3 = incr(v.w);
        acc = (i == 0) ? d0 : __fadd_rn(acc, d0);
        acc = __fadd_rn(acc, d1);
        acc = __fadd_rn(acc, d2);
        acc = __fadd_rn(acc, d3);
    }
    g_S1[j] = acc;
}

// ---------------------------------------------------------------------------
// Kernel B: recursive 16-ary blocked scan of S1 -> off1 offsets
// ---------------------------------------------------------------------------
__global__ void __launch_bounds__(256) offsets_kernel(){
    __shared__ float sI2[NB1];
    __shared__ float sI3[NB2P];
    __shared__ float sO4[NB3];
    const int row = blockIdx.x, tid = threadIdx.x, nt = 256;
    const float* S1 = g_S1 + row * NB1;
    for (int i = tid; i < NB1; i += nt) sI2[i] = S1[i];
    __syncthreads();

    if (tid < NB2){
        int b = tid * BLK;
        float acc = sI2[b];
        #pragma unroll
        for (int i = 1; i < BLK; i++){ acc = __fadd_rn(acc, sI2[b+i]); sI2[b+i] = acc; }
    }
    __syncthreads();

    if (tid < NB3){
        int b = tid * BLK;
        float acc = 0.0f;
        #pragma unroll
        for (int i = 0; i < BLK; i++){
            int m = b + i;
            float s2 = (m < NB2) ? sI2[m*BLK + (BLK-1)] : 0.0f;
            acc = (i == 0) ? s2 : __fadd_rn(acc, s2);
            sI3[m] = acc;
        }
    }
    __syncthreads();

    if (tid == 0){
        float acc = 0.0f;
        #pragma unroll
        for (int p = 0; p < NB3; p++){
            float s3 = sI3[p*BLK + (BLK-1)];
            acc = (p == 0) ? s3 : __fadd_rn(acc, s3);
            sO4[p] = acc;
        }
    }
    __syncthreads();

    float* off1 = g_off1 + row * NB1;
    for (int j = tid; j < NB1; j += nt){
        float v;
        if (j == 0) v = 0.0f;
        else {
            int jm = j - 1, q = jm >> 4;
            float o3e;
            if (q == 0) o3e = 0.0f;
            else {
                int qm = q - 1, p = qm >> 4;
                float o4e = (p == 0) ? 0.0f : sO4[p-1];
                o3e = __fadd_rn(o4e, sI3[qm]);
            }
            v = __fadd_rn(o3e, sI2[jm]);
        }
        off1[j] = v;
    }
}

// ---------------------------------------------------------------------------
// Oscillator: 2 adjacent samples per thread (ILP-2). One DP sincos per thread
// (sample B via exact-delta Taylor rotation). Tail rows filled with -100
// (hfast(-100) == 0 exactly) -> uniform maskless loop. fp16 raw-amp staging.
// ---------------------------------------------------------------------------
__global__ void __launch_bounds__(TPB, 6) osc_kernel(
    const float* __restrict__ f0,
    const float* __restrict__ amps,
    const float* __restrict__ phase,
    float* __restrict__ out)
{
    __shared__ __half sX[TILE * 65];   // raw amps (fp16), linear, tail-masked
    __shared__ float  sD[TILE];
    __shared__ float  sOFF[TILE / BLK];
    const int tid    = threadIdx.x;
    const int nchunk = NSAMP / TILE;
    const int b      = blockIdx.x / nchunk;
    const int t0     = (blockIdx.x % nchunk) * TILE;
    const int sbase  = b * NSAMP + t0;

    {   // stage 8 floats/iter: 2x LDG.128 -> 4x cvt.f16x2 -> 1x STS.128
        const float4* gsrc = (const float4*)(amps + (size_t)sbase * 65);
        uint4* sdst = (uint4*)sX;
        #pragma unroll 4
        for (int i = tid; i < TILE * 65 / 8; i += TPB){
            float4 a = gsrc[2*i], c = gsrc[2*i+1];
            uint4 hp;
            hp.x = f2h2(a.x, a.y);
            hp.y = f2h2(a.z, a.w);
            hp.z = f2h2(c.x, c.y);
            hp.w = f2h2(c.z, c.w);
            sdst[i] = hp;
        }
    }
    const int iA  = 2 * tid;
    const int idx = sbase + iA;
    const float2 f02 = *(const float2*)(f0 + idx);
    sD[iA]   = incr(f02.x);
    sD[iA+1] = incr(f02.y);
    if (tid < TILE / BLK) sOFF[tid] = g_off1[(sbase >> 4) + tid];
    __syncthreads();

    // bit-exact thetas: within-16 ascending fold; incB = fl(incA + dB)
    const int g = iA >> 4, i15 = iA & 15;
    float inc = sD[g * BLK];
    for (int i = 1; i <= i15; ++i) inc = __fadd_rn(inc, sD[g * BLK + i]);
    const float incB = __fadd_rn(inc, sD[iA + 1]);
    const float ph = phase[b];
    const float thetaA = __fadd_rn(__fadd_rn(sOFF[g], inc),  ph);
    const float thetaB = __fadd_rn(__fadd_rn(sOFF[g], incB), ph);

    // one DP mod-pi + poly sincos (sample A)
    const double thd = (double)thetaA;
    const double qd  = rint(thd * 0.31830988618379067154);
    const int    q   = (int)qd;
    const double rd  = fma(-3.14159265358979323846, qd, thd);
    const float  r   = (float)rd;
    const float  rl  = (float)(rd - (double)r);

    const float r2 = r * r;
    float p = -2.5052108385441718e-8f;
    p = fmaf(p, r2,  2.7557319223985893e-6f);
    p = fmaf(p, r2, -1.9841269841269841e-4f);
    p = fmaf(p, r2,  8.3333333333333333e-3f);
    p = fmaf(p, r2, -1.6666666666666667e-1f);
    const float sp = fmaf(r * r2, p, r);
    float qq = 2.0876756987868099e-9f;
    qq = fmaf(qq, r2, -2.7557319223985888e-7f);
    qq = fmaf(qq, r2,  2.4801587301587302e-5f);
    qq = fmaf(qq, r2, -1.3888888888888889e-3f);
    qq = fmaf(qq, r2,  4.1666666666666664e-2f);
    qq = fmaf(qq, r2, -0.5f);
    const float cp = fmaf(qq, r2, 1.0f);

    float s1A = fmaf(cp,  rl, sp);
    float c1A = fmaf(-sp, rl, cp);
    const float sg = (q & 1) ? -1.0f : 1.0f;
    s1A *= sg; c1A *= sg;

    // sample B sincos via exact small delta (Sterbenz): Taylor deg5/4
    const float dl = __fsub_rn(thetaB, thetaA);
    const float d2 = dl * dl;
    const float sd = dl * fmaf(d2, fmaf(d2, 8.3333333333e-3f, -1.6666666667e-1f), 1.0f);
    const float cd = fmaf(d2, fmaf(d2, 4.1666666667e-2f, -0.5f), 1.0f);
    const float s1B = fmaf(s1A, cd,  c1A * sd);
    const float c1B = fmaf(c1A, cd, -(s1A * sd));

    const float s2A = 2.0f * s1A * c1A;
    const float c2A = fmaf(-2.0f * s1A, s1A, 1.0f);
    const float s2B = 2.0f * s1B * c1B;
    const float c2B = fmaf(-2.0f * s1B, s1B, 1.0f);

    // anti-alias cutoffs (branchless exact)
    int kcA = (int)__fdividef(22050.0f, f02.x);
    kcA += (__fmul_rn(f02.x, (float)(kcA+1)) <  22050.0f) ? 1 : 0;
    kcA -= (__fmul_rn(f02.x, (float)kcA)     >= 22050.0f) ? 1 : 0;
    kcA = (kcA > 64) ? 64 : kcA;
    int kcB = (int)__fdividef(22050.0f, f02.y);
    kcB += (__fmul_rn(f02.y, (float)(kcB+1)) <  22050.0f) ? 1 : 0;
    kcB -= (__fmul_rn(f02.y, (float)kcB)     >= 22050.0f) ? 1 : 0;
    kcB = (kcB > 64) ? 64 : kcB;

    __half* rowA = sX + iA * 65;       // rowA[0]=ta input, rowA[k]=h input
    __half* rowB = rowA + 65;
    const float taA = hfull(__half2float(rowA[0]));
    const float taB = hfull(__half2float(rowB[0]));

    // tail-mask own rows: fill k > kc with -100 (hfast(-100) == 0 exactly)
    const __half HM = __float2half(-100.0f);
    for (int k = kcA + 1; k <= 64; ++k) rowA[k] = HM;
    for (int k = kcB + 1; k <= 64; ++k) rowB[k] = HM;

    u64 SA = pack2(s1A, s2A), CA = pack2(c1A, c2A);
    u64 SB = pack2(s1B, s2B), CB = pack2(c1B, c2B);
    const u64 S2Ak = pack2(s2A, s2A), C2Ak = pack2(c2A, c2A), NS2Ak = pack2(-s2A, -s2A);
    const u64 S2Bk = pack2(s2B, s2B), C2Bk = pack2(c2B, c2B), NS2Bk = pack2(-s2B, -s2B);
    const u64 THA = pack2(thetaA, thetaA), NTHA = pack2(-thetaA, -thetaA);
    const u64 THB = pack2(thetaB, thetaB), NTHB = pack2(-thetaB, -thetaB);
    const u64 TWO = pack2(2.0f, 2.0f);
    u64 KF = pack2(1.0f, 2.0f);
    u64 accA = pack2(0.0f, 0.0f), sumA = accA;
    u64 accB = accA, sumB = accA;

    // 16 groups x 2 pairs; h batched 4 per sample (8 indep MUFU chains)
    #pragma unroll
    for (int gb = 0; gb < 16; ++gb){
        float hA[4], hB[4];
        #pragma unroll
        for (int i = 0; i < 4; ++i){
            hA[i] = hfast(__half2float(rowA[gb*4 + 1 + i]));
            hB[i] = hfast(__half2float(rowB[gb*4 + 1 + i]));
        }
        #pragma unroll
        for (int jj = 0; jj < 2; ++jj){
            u64 h2A = pack2(hA[2*jj], hA[2*jj+1]);
            u64 h2B = pack2(hB[2*jj], hB[2*jj+1]);
            sumA = add2(sumA, h2A);
            sumB = add2(sumB, h2B);

            u64 aA  = mul2(THA, KF);
            u64 eA  = fma2(NTHA, KF, aA);
            u64 svA = fma2(CA, eA, SA);
            accA = fma2(h2A, svA, accA);

            u64 aB  = mul2(THB, KF);
            u64 eB  = fma2(NTHB, KF, aB);
            u64 svB = fma2(CB, eB, SB);
            accB = fma2(h2B, svB, accB);

            u64 SnA = fma2(CA, S2Ak, mul2(SA, C2Ak));
            u64 CnA = fma2(SA, NS2Ak, mul2(CA, C2Ak));
            SA = SnA; CA = CnA;
            u64 SnB = fma2(CB, S2Bk, mul2(SB, C2Bk));
            u64 CnB = fma2(SB, NS2Bk, mul2(CB, C2Bk));
            SB = SnB; CB = CnB;

            KF = add2(KF, TWO);
        }
    }

    float a0, a1, m0, m1;
    float2 o;
    unpack2(accA, a0, a1); unpack2(sumA, m0, m1);
    o.x = (a0 + a1) * (taA / ((m0 + m1) + 1e-5f));
    unpack2(accB, a0, a1); unpack2(sumB, m0, m1);
    o.y = (a0 + a1) * (taB / ((m0 + m1) + 1e-5f));
    *(float2*)(out + idx) = o;
}

extern "C" void kernel_launch(void* const* d_in, const int* in_sizes, int n_in,
                              void* d_out, int out_size)
{
    const float* f0    = (const float*)d_in[0];
    const float* amps  = (const float*)d_in[1];
    const float* phase = (const float*)d_in[2];
    float* out = (float*)d_out;

    prep_kernel<<<(BS*NB1)/TPB, TPB>>>(f0);
    offsets_kernel<<<BS, 256>>>();
    osc_kernel<<<(BS * NSAMP) / TILE, TPB>>>(f0, amps, phase, out);
}

// round 16
// speedup vs baseline: 1.1989x; 1.1989x over previous
#include <cuda_runtime.h>
#include <cuda_fp16.h>
#include <math.h>

#define BS 32
#define NSAMP 64000
#define NTOT (BS*NSAMP)
#define TPB 128
#define BLK 16                 // XLA ReduceWindowRewriter base_length
#define NB1 (NSAMP/BLK)        // 4000 level-1 blocks per row
#define NB2 (NB1/BLK)          // 250 level-2 blocks
#define NB2P 256               // padded to multiple of 16
#define NB3 (NB2P/BLK)         // 16

__device__ float g_S1[BS*NB1];   // level-1 block sums
__device__ float g_O3[BS*NB2];   // level-3 scan values O3[q] per row

typedef unsigned long long u64;

__device__ __forceinline__ float ex2f(float x){ float r; asm("ex2.approx.f32 %0, %1;":"=f"(r):"f"(x)); return r; }
__device__ __forceinline__ float lg2f(float x){ float r; asm("lg2.approx.f32 %0, %1;":"=f"(r):"f"(x)); return r; }

// ---- packed f32x2 helpers ----
__device__ __forceinline__ u64 pack2(float lo, float hi){ u64 r; asm("mov.b64 %0, {%1,%2};":"=l"(r):"f"(lo),"f"(hi)); return r; }
__device__ __forceinline__ void unpack2(u64 v, float& lo, float& hi){ asm("mov.b64 {%0,%1}, %2;":"=f"(lo),"=f"(hi):"l"(v)); }
__device__ __forceinline__ u64 fma2(u64 a,u64 b,u64 c){ u64 r; asm("fma.rn.f32x2 %0,%1,%2,%3;":"=l"(r):"l"(a),"l"(b),"l"(c)); return r; }
__device__ __forceinline__ u64 mul2(u64 a,u64 b){ u64 r; asm("mul.rn.f32x2 %0,%1,%2;":"=l"(r):"l"(a),"l"(b)); return r; }
__device__ __forceinline__ u64 add2(u64 a,u64 b){ u64 r; asm("add.rn.f32x2 %0,%1,%2;":"=l"(r):"l"(a),"l"(b)); return r; }

// pack two f32 into a half2 register in one cvt
__device__ __forceinline__ unsigned int f2h2(float a, float b){
    unsigned int r; asm("cvt.rn.f16x2.f32 %0, %2, %1;":"=r"(r):"f"(a),"f"(b)); return r;
}

// 2*sigmoid(x)^ln10 (merged tail; +1e-7 dropped: <=1e-7 abs error)
__device__ __forceinline__ float hfast(float x){
    float e = ex2f(-1.4426950408889634f * x);
    float u = lg2f(1.0f + e);
    return ex2f(fmaf(u, -2.3025850929940457f, 1.0f));
}
// full variant for total_amplitude
__device__ __forceinline__ float hfull(float x){
    float e = ex2f(-1.4426950408889634f * x);
    float u = lg2f(1.0f + e);
    return fmaf(2.0f, ex2f(-2.3025850929940457f * u), 1e-7f);
}

// increment: fast-math (arcp) form
__device__ __forceinline__ float incr(float f){
    const float RINV = 1.0f / 44100.0f;
    return __fmul_rn(__fmul_rn(6.283185307179586f, f), RINV);
}

// ---------------------------------------------------------------------------
// Kernel A: level-1 block sums S1 (ascending fold within each 16-block)
// ---------------------------------------------------------------------------
__global__ void __launch_bounds__(TPB) prep_kernel(const float* __restrict__ f0){
    int j = blockIdx.x * blockDim.x + threadIdx.x;
    if (j >= BS * NB1) return;
    const float4* fp = (const float4*)(f0 + (size_t)j * BLK);
    float acc = 0.0f;
    #pragma unroll
    for (int i = 0; i < BLK/4; i++){
        float4 v = fp[i];
        float d0 = incr(v.x), d1 = incr(v.y), d2 = incr(v.z), d3 = incr(v.w);
        acc = (i == 0) ? d0 : __fadd_rn(acc, d0);
        acc = __fadd_rn(acc, d1);
        acc = __fadd_rn(acc, d2);
        acc = __fadd_rn(acc, d3);
    }
    g_S1[j] = acc;
}

// ---------------------------------------------------------------------------
// Kernel B: per row — levels 2..4 of the blocked scan, emitting O3[q] only.
// (Level-1 offsets are reconstructed inside osc from S1 + O3.)
//   S2[q]  = fold16 of S1 within level-2 block q (250, padded 0 to 256)
//   I3[m]  = ascending inclusive fold of S2 within 16-blocks
//   O4[p]  = sequential scan of the 16 I3 block-ends
//   O3[q]  = I3[q]                  (q>>4 == 0)
//          = fl(O4[q>>4 - 1] + I3[q]) otherwise
// ---------------------------------------------------------------------------
__global__ void __launch_bounds__(256) lvl_kernel(){
    __shared__ float sS2[NB2P];
    __shared__ float sI3[NB2P];
    __shared__ float sO4[NB3];
    const int row = blockIdx.x, tid = threadIdx.x;
    const float* S1 = g_S1 + row * NB1;

    if (tid < NB2P){
        float acc = 0.0f;
        if (tid < NB2){
            int bb = tid * BLK;
            acc = S1[bb];
            #pragma unroll
            for (int i = 1; i < BLK; i++) acc = __fadd_rn(acc, S1[bb + i]);
        }
        sS2[tid] = acc;   // padding entries exactly 0
    }
    __syncthreads();

    if (tid < NB3){
        int bb = tid * BLK;
        float acc = 0.0f;
        #pragma unroll
        for (int i = 0; i < BLK; i++){
            float s2 = sS2[bb + i];
            acc = (i == 0) ? s2 : __fadd_rn(acc, s2);
            sI3[bb + i] = acc;
        }
    }
    __syncthreads();

    if (tid == 0){
        float acc = 0.0f;
        #pragma unroll
        for (int p = 0; p < NB3; p++){
            float s3 = sI3[p*BLK + (BLK-1)];
            acc = (p == 0) ? s3 : __fadd_rn(acc, s3);
            sO4[p] = acc;
        }
    }
    __syncthreads();

    if (tid < NB2){
        int p = tid >> 4;
        float v = (p == 0) ? sI3[tid] : __fadd_rn(sO4[p-1], sI3[tid]);
        g_O3[row * NB2 + tid] = v;
    }
}

// ---------------------------------------------------------------------------
// Oscillator (R12 winner core): fp16 raw-amp staging, hfast batched 8,
// packed rotation + fl(theta*k) correction. Level-1 offsets computed in-block:
//   off1[j] = 0                         (j == 0)
//           = fl(O3excl(q) + fold(S1[q*16 .. j-1]))   q = (j-1)>>4
// ---------------------------------------------------------------------------
__global__ void __launch_bounds__(TPB, 8) osc_kernel(
    const float* __restrict__ f0,
    const float* __restrict__ amps,
    const float* __restrict__ phase,
    float* __restrict__ out)
{
    __shared__ __half sX[TPB * 65];    // raw amps, linear (mirrors gmem)
    __shared__ float  sD[TPB];
    __shared__ float  sOFF[TPB / BLK];
    const int tid    = threadIdx.x;
    const int nchunk = NSAMP / TPB;
    const int b      = blockIdx.x / nchunk;
    const int t0     = (blockIdx.x % nchunk) * TPB;
    const int sbase  = b * NSAMP + t0;

    {   // stage 8 floats/iter: 2x LDG.128 -> 4x cvt.f16x2 -> 1x STS.128
        const float4* gsrc = (const float4*)(amps + (size_t)sbase * 65);
        uint4* sdst = (uint4*)sX;
        #pragma unroll 3
        for (int i = tid; i < TPB * 65 / 8; i += TPB){
            float4 a = gsrc[2*i], c = gsrc[2*i+1];
            uint4 hp;
            hp.x = f2h2(a.x, a.y);
            hp.y = f2h2(a.z, a.w);
            hp.z = f2h2(c.x, c.y);
            hp.w = f2h2(c.z, c.w);
            sdst[i] = hp;
        }
    }
    const int idx   = sbase + tid;
    const float f0v = f0[idx];
    sD[tid] = incr(f0v);

    // reconstruct the 8 level-1 offsets for this block (bit-exact mirror of
    // the old offsets kernel: off1[j] = fl(o3e + I2[j-1]))
    if (tid < TPB / BLK){
        const int j = (t0 >> 4) + tid;       // row-local level-1 block index
        float off;
        if (j == 0) off = 0.0f;
        else {
            const int jm = j - 1, qq2 = jm >> 4, base = qq2 << 4;
            const float* S1r = g_S1 + b * NB1;
            float acc = S1r[base];
            for (int i = base + 1; i <= jm; ++i) acc = __fadd_rn(acc, S1r[i]);
            float o3e = (qq2 == 0) ? 0.0f : g_O3[b * NB2 + qq2 - 1];
            off = __fadd_rn(o3e, acc);
        }
        sOFF[tid] = off;
    }
    __syncthreads();

    // bit-exact omega/theta (within-16 ascending fold + one offset add)
    const int g = tid >> 4, i15 = tid & 15;
    float inc = sD[g * BLK];
    for (int i = 1; i <= i15; ++i) inc = __fadd_rn(inc, sD[g * BLK + i]);
    const float omega = __fadd_rn(sOFF[g], inc);
    const float theta = __fadd_rn(omega, phase[b]);

    // accurate sincos(theta): mod-pi in double
    const double thd = (double)theta;
    const double qd  = rint(thd * 0.31830988618379067154);
    const int    q   = (int)qd;
    const double rd  = fma(-3.14159265358979323846, qd, thd);
    const float  r   = (float)rd;
    const float  rl  = (float)(rd - (double)r);

    const float r2 = r * r;
    float p = -2.5052108385441718e-8f;
    p = fmaf(p, r2,  2.7557319223985893e-6f);
    p = fmaf(p, r2, -1.9841269841269841e-4f);
    p = fmaf(p, r2,  8.3333333333333333e-3f);
    p = fmaf(p, r2, -1.6666666666666667e-1f);
    const float sp = fmaf(r * r2, p, r);
    float qq = 2.0876756987868099e-9f;
    qq = fmaf(qq, r2, -2.7557319223985888e-7f);
    qq = fmaf(qq, r2,  2.4801587301587302e-5f);
    qq = fmaf(qq, r2, -1.3888888888888889e-3f);
    qq = fmaf(qq, r2,  4.1666666666666664e-2f);
    qq = fmaf(qq, r2, -0.5f);
    const float cp = fmaf(qq, r2, 1.0f);

    float s1 = fmaf(cp,  rl, sp);
    float c1 = fmaf(-sp, rl, cp);
    const float sg = (q & 1) ? -1.0f : 1.0f;
    s1 *= sg; c1 *= sg;

    const float s2v = 2.0f * s1 * c1;
    const float c2v = fmaf(-2.0f * s1, s1, 1.0f);

    // branchless anti-alias cutoff: largest k with fl(f0*k) < 22050
    int kc = (int)__fdividef(22050.0f, f0v);
    kc += (__fmul_rn(f0v, (float)(kc+1)) <  22050.0f) ? 1 : 0;
    kc -= (__fmul_rn(f0v, (float)kc)     >= 22050.0f) ? 1 : 0;
    kc = (kc > 64) ? 64 : kc;

    const __half* my = sX + tid * 65;  // my[0]=raw ta input, my[k]=raw h input
    const float ta = hfull(__half2float(my[0]));

    u64 S   = pack2(s1,  s2v);
    u64 C   = pack2(c1,  c2v);
    const u64 S2  = pack2(s2v,  s2v);
    const u64 C2  = pack2(c2v,  c2v);
    const u64 NS2 = pack2(-s2v, -s2v);
    const u64 TH  = pack2(theta,  theta);
    const u64 NTH = pack2(-theta, -theta);
    const u64 TWO = pack2(2.0f, 2.0f);
    u64 KF  = pack2(1.0f, 2.0f);
    u64 acc2 = pack2(0.0f, 0.0f);
    u64 sum2 = pack2(0.0f, 0.0f);

    // 8 groups of 8 harmonics; batch hfast over 8 for MUFU ILP.
    // Groups 0..4 cover k=1..40 (< 45) -> never masked.
    #pragma unroll
    for (int gb = 0; gb < 8; ++gb){
        float h[8];
        #pragma unroll
        for (int i = 0; i < 8; ++i)
            h[i] = hfast(__half2float(my[gb*8 + 1 + i]));

        #pragma unroll
        for (int jj = 0; jj < 4; ++jj){
            const int kA = gb*8 + 2*jj + 1;
            float hA = h[2*jj], hB = h[2*jj+1];
            if (gb >= 5){                       // masking only possible here
                hA = (kA     <= kc) ? hA : 0.0f;
                hB = (kA + 1 <= kc) ? hB : 0.0f;
            }
            u64 h2 = pack2(hA, hB);
            sum2 = add2(sum2, h2);

            u64 a2  = mul2(TH, KF);
            u64 er2 = fma2(NTH, KF, a2);
            u64 sv2 = fma2(C, er2, S);      // sin(fl(k*theta)) ~= s + c*e
            acc2 = fma2(h2, sv2, acc2);

            u64 Sn = fma2(C, S2, mul2(S, C2));
            u64 Cn = fma2(S, NS2, mul2(C, C2));
            S = Sn; C = Cn;
            KF = add2(KF, TWO);
        }
    }

    float aA, aB, smA, smB;
    unpack2(acc2, aA, aB);
    unpack2(sum2, smA, smB);
    out[idx] = (aA + aB) * (ta / ((smA + smB) + 1e-5f));
}

extern "C" void kernel_launch(void* const* d_in, const int* in_sizes, int n_in,
                              void* d_out, int out_size)
{
    const float* f0    = (const float*)d_in[0];
    const float* amps  = (const float*)d_in[1];
    const float* phase = (const float*)d_in[2];
    float* out = (float*)d_out;

    prep_kernel<<<(BS*NB1)/TPB, TPB>>>(f0);
    lvl_kernel<<<BS, 256>>>();
    osc_kernel<<<(BS * NSAMP) / TPB, TPB>>>(f0, amps, phase, out);
}

// round 17
// speedup vs baseline: 1.2343x; 1.0295x over previous
#include <cuda_runtime.h>
#include <cuda_fp16.h>
#include <math.h>

#define BS 32
#define NSAMP 64000
#define NTOT (BS*NSAMP)
#define TPB 128
#define BLK 16                 // XLA ReduceWindowRewriter base_length
#define NB1 (NSAMP/BLK)        // 4000 level-1 blocks per row
#define NB2 (NB1/BLK)          // 250 level-2 blocks
#define NB2P 256               // padded to multiple of 16
#define NB3 (NB2P/BLK)         // 16

__device__ float g_S1[BS*NB1];   // level-1 block sums
__device__ float g_off1[BS*NB1]; // exclusive offset for each level-1 block

typedef unsigned long long u64;

__device__ __forceinline__ float ex2f(float x){ float r; asm("ex2.approx.f32 %0, %1;":"=f"(r):"f"(x)); return r; }
__device__ __forceinline__ float lg2f(float x){ float r; asm("lg2.approx.f32 %0, %1;":"=f"(r):"f"(x)); return r; }

// ---- packed f32x2 helpers ----
__device__ __forceinline__ u64 pack2(float lo, float hi){ u64 r; asm("mov.b64 %0, {%1,%2};":"=l"(r):"f"(lo),"f"(hi)); return r; }
__device__ __forceinline__ void unpack2(u64 v, float& lo, float& hi){ asm("mov.b64 {%0,%1}, %2;":"=f"(lo),"=f"(hi):"l"(v)); }
__device__ __forceinline__ u64 fma2(u64 a,u64 b,u64 c){ u64 r; asm("fma.rn.f32x2 %0,%1,%2,%3;":"=l"(r):"l"(a),"l"(b),"l"(c)); return r; }
__device__ __forceinline__ u64 mul2(u64 a,u64 b){ u64 r; asm("mul.rn.f32x2 %0,%1,%2;":"=l"(r):"l"(a),"l"(b)); return r; }
__device__ __forceinline__ u64 add2(u64 a,u64 b){ u64 r; asm("add.rn.f32x2 %0,%1,%2;":"=l"(r):"l"(a),"l"(b)); return r; }

// pack two f32 into a half2 register in one cvt
__device__ __forceinline__ unsigned int f2h2(float a, float b){
    unsigned int r; asm("cvt.rn.f16x2.f32 %0, %2, %1;":"=r"(r):"f"(a),"f"(b)); return r;
}

// 2*sigmoid(x)^ln10 (merged tail; +1e-7 dropped: <=1e-7 abs error)
__device__ __forceinline__ float hfast(float x){
    float e = ex2f(-1.4426950408889634f * x);
    float u = lg2f(1.0f + e);
    return ex2f(fmaf(u, -2.3025850929940457f, 1.0f));
}
// full variant for total_amplitude
__device__ __forceinline__ float hfull(float x){
    float e = ex2f(-1.4426950408889634f * x);
    float u = lg2f(1.0f + e);
    return fmaf(2.0f, ex2f(-2.3025850929940457f * u), 1e-7f);
}

// increment: fast-math (arcp) form
__device__ __forceinline__ float incr(float f){
    const float RINV = 1.0f / 44100.0f;
    return __fmul_rn(__fmul_rn(6.283185307179586f, f), RINV);
}

// ---------------------------------------------------------------------------
// Kernel A: level-1 block sums S1
// ---------------------------------------------------------------------------
__global__ void __launch_bounds__(TPB) prep_kernel(const float* __restrict__ f0){
    int j = blockIdx.x * blockDim.x + threadIdx.x;
    if (j >= BS * NB1) return;
    const float4* fp = (const float4*)(f0 + (size_t)j * BLK);
    float acc = 0.0f;
    #pragma unroll
    for (int i = 0; i < BLK/4; i++){
        float4 v = fp[i];
        float d0 = incr(v.x), d1 = incr(v.y), d2 = incr(v.z), d3 = incr(v.w);
        acc = (i == 0) ? d0 : __fadd_rn(acc, d0);
        acc = __fadd_rn(acc, d1);
        acc = __fadd_rn(acc, d2);
        acc = __fadd_rn(acc, d3);
    }
    g_S1[j] = acc;
}

// ---------------------------------------------------------------------------
// Kernel B: recursive 16-ary blocked scan of S1 -> off1 offsets (R13 version)
// ---------------------------------------------------------------------------
__global__ void __launch_bounds__(256) offsets_kernel(){
    __shared__ float sI2[NB1];
    __shared__ float sI3[NB2P];
    __shared__ float sO4[NB3];
    const int row = blockIdx.x, tid = threadIdx.x, nt = 256;
    const float* S1 = g_S1 + row * NB1;
    for (int i = tid; i < NB1; i += nt) sI2[i] = S1[i];
    __syncthreads();

    if (tid < NB2){
        int b = tid * BLK;
        float acc = sI2[b];
        #pragma unroll
        for (int i = 1; i < BLK; i++){ acc = __fadd_rn(acc, sI2[b+i]); sI2[b+i] = acc; }
    }
    __syncthreads();

    if (tid < NB3){
        int b = tid * BLK;
        float acc = 0.0f;
        #pragma unroll
        for (int i = 0; i < BLK; i++){
            int m = b + i;
            float s2 = (m < NB2) ? sI2[m*BLK + (BLK-1)] : 0.0f;
            acc = (i == 0) ? s2 : __fadd_rn(acc, s2);
            sI3[m] = acc;
        }
    }
    __syncthreads();

    if (tid == 0){
        float acc = 0.0f;
        #pragma unroll
        for (int p = 0; p < NB3; p++){
            float s3 = sI3[p*BLK + (BLK-1)];
            acc = (p == 0) ? s3 : __fadd_rn(acc, s3);
            sO4[p] = acc;
        }
    }
    __syncthreads();

    float* off1 = g_off1 + row * NB1;
    for (int j = tid; j < NB1; j += nt){
        float v;
        if (j == 0) v = 0.0f;
        else {
            int jm = j - 1, q = jm >> 4;
            float o3e;
            if (q == 0) o3e = 0.0f;
            else {
                int qm = q - 1, p = qm >> 4;
                float o4e = (p == 0) ? 0.0f : sO4[p-1];
                o3e = __fadd_rn(o4e, sI3[qm]);
            }
            v = __fadd_rn(o3e, sI2[jm]);
        }
        off1[j] = v;
    }
}

// ---------------------------------------------------------------------------
// Oscillator (R12 core, DP-free): fp16 raw-amp staging, hfast batched 8,
// packed rotation + fl(theta*k) correction. mod-pi via FP32 Cody-Waite.
// ---------------------------------------------------------------------------
__global__ void __launch_bounds__(TPB, 8) osc_kernel(
    const float* __restrict__ f0,
    const float* __restrict__ amps,
    const float* __restrict__ phase,
    float* __restrict__ out)
{
    __shared__ __half sX[TPB * 65];    // raw amps, linear (mirrors gmem)
    __shared__ float  sD[TPB];
    __shared__ float  sOFF[TPB / BLK];
    const int tid    = threadIdx.x;
    const int nchunk = NSAMP / TPB;
    const int b      = blockIdx.x / nchunk;
    const int t0     = (blockIdx.x % nchunk) * TPB;
    const int sbase  = b * NSAMP + t0;

    {   // stage 8 floats/iter: 2x LDG.128 -> 4x cvt.f16x2 -> 1x STS.128
        const float4* gsrc = (const float4*)(amps + (size_t)sbase * 65);
        uint4* sdst = (uint4*)sX;
        #pragma unroll 3
        for (int i = tid; i < TPB * 65 / 8; i += TPB){
            float4 a = gsrc[2*i], c = gsrc[2*i+1];
            uint4 hp;
            hp.x = f2h2(a.x, a.y);
            hp.y = f2h2(a.z, a.w);
            hp.z = f2h2(c.x, c.y);
            hp.w = f2h2(c.z, c.w);
            sdst[i] = hp;
        }
    }
    const int idx   = sbase + tid;
    const float f0v = f0[idx];
    sD[tid] = incr(f0v);
    if (tid < TPB / BLK) sOFF[tid] = g_off1[(sbase >> 4) + tid];
    __syncthreads();

    // bit-exact omega/theta (within-16 ascending fold + one offset add)
    const int g = tid >> 4, i15 = tid & 15;
    float inc = sD[g * BLK];
    for (int i = 1; i <= i15; ++i) inc = __fadd_rn(inc, sD[g * BLK + i]);
    const float omega = __fadd_rn(sOFF[g], inc);
    const float theta = __fadd_rn(omega, phase[b]);

    // mod-pi in pure FP32 (2-term Cody-Waite; q <= 1404 fits 11 bits so
    // q*PI1 is exact with 12-bit PI1; residual pi-PI1-PI2 ~3e-11 * q < 5e-8)
    const float qf = rintf(theta * 0.31830988618379067f);
    const int   q  = (int)qf;
    float r = fmaf(-3.140625f, qf, theta);          // exact product, 1 rounding
    r = fmaf(-9.67653590e-4f, qf, r);               // |r| <= pi/2 + ~4e-4

    const float r2 = r * r;
    float p = -2.5052108385441718e-8f;
    p = fmaf(p, r2,  2.7557319223985893e-6f);
    p = fmaf(p, r2, -1.9841269841269841e-4f);
    p = fmaf(p, r2,  8.3333333333333333e-3f);
    p = fmaf(p, r2, -1.6666666666666667e-1f);
    const float sp = fmaf(r * r2, p, r);
    float qq = 2.0876756987868099e-9f;
    qq = fmaf(qq, r2, -2.7557319223985888e-7f);
    qq = fmaf(qq, r2,  2.4801587301587302e-5f);
    qq = fmaf(qq, r2, -1.3888888888888889e-3f);
    qq = fmaf(qq, r2,  4.1666666666666664e-2f);
    qq = fmaf(qq, r2, -0.5f);
    const float cp = fmaf(qq, r2, 1.0f);

    const float sg = (q & 1) ? -1.0f : 1.0f;
    const float s1 = sp * sg;
    const float c1 = cp * sg;

    const float s2v = 2.0f * s1 * c1;
    const float c2v = fmaf(-2.0f * s1, s1, 1.0f);

    // branchless anti-alias cutoff: largest k with fl(f0*k) < 22050
    int kc = (int)__fdividef(22050.0f, f0v);
    kc += (__fmul_rn(f0v, (float)(kc+1)) <  22050.0f) ? 1 : 0;
    kc -= (__fmul_rn(f0v, (float)kc)     >= 22050.0f) ? 1 : 0;
    kc = (kc > 64) ? 64 : kc;

    const __half* my = sX + tid * 65;  // my[0]=raw ta input, my[k]=raw h input
    const float ta = hfull(__half2float(my[0]));

    u64 S   = pack2(s1,  s2v);
    u64 C   = pack2(c1,  c2v);
    const u64 S2  = pack2(s2v,  s2v);
    const u64 C2  = pack2(c2v,  c2v);
    const u64 NS2 = pack2(-s2v, -s2v);
    const u64 TH  = pack2(theta,  theta);
    const u64 NTH = pack2(-theta, -theta);
    const u64 TWO = pack2(2.0f, 2.0f);
    u64 KF  = pack2(1.0f, 2.0f);
    u64 acc2 = pack2(0.0f, 0.0f);
    u64 sum2 = pack2(0.0f, 0.0f);

    // 8 groups of 8 harmonics; batch hfast over 8 for MUFU ILP.
    // Groups 0..4 cover k=1..40 (< 45) -> never masked.
    #pragma unroll
    for (int gb = 0; gb < 8; ++gb){
        float h[8];
        #pragma unroll
        for (int i = 0; i < 8; ++i)
            h[i] = hfast(__half2float(my[gb*8 + 1 + i]));

        #pragma unroll
        for (int jj = 0; jj < 4; ++jj){
            const int kA = gb*8 + 2*jj + 1;
            float hA = h[2*jj], hB = h[2*jj+1];
            if (gb >= 5){                       // masking only possible here
                hA = (kA     <= kc) ? hA : 0.0f;
                hB = (kA + 1 <= kc) ? hB : 0.0f;
            }
            u64 h2 = pack2(hA, hB);
            sum2 = add2(sum2, h2);

            u64 a2  = mul2(TH, KF);
            u64 er2 = fma2(NTH, KF, a2);
            u64 sv2 = fma2(C, er2, S);      // sin(fl(k*theta)) ~= s + c*e
            acc2 = fma2(h2, sv2, acc2);

            u64 Sn = fma2(C, S2, mul2(S, C2));
            u64 Cn = fma2(S, NS2, mul2(C, C2));
            S = Sn; C = Cn;
            KF = add2(KF, TWO);
        }
    }

    float aA, aB, smA, smB;
    unpack2(acc2, aA, aB);
    unpack2(sum2, smA, smB);
    out[idx] = (aA + aB) * (ta / ((smA + smB) + 1e-5f));
}

extern "C" void kernel_launch(void* const* d_in, const int* in_sizes, int n_in,
                              void* d_out, int out_size)
{
    const float* f0    = (const float*)d_in[0];
    const float* amps  = (const float*)d_in[1];
    const float* phase = (const float*)d_in[2];
    float* out = (float*)d_out;

    prep_kernel<<<(BS*NB1)/TPB, TPB>>>(f0);
    offsets_kernel<<<BS, 256>>>();
    osc_kernel<<<(BS * NSAMP) / TPB, TPB>>>(f0, amps, phase, out);
}